// round 16
// baseline (speedup 1.0000x reference)
#include <cuda_runtime.h>
#include <cuda_fp16.h>
#include <cstdint>

#define U_NODES 100000
#define I_NODES 150000
#define N_NODES (U_NODES + I_NODES)
#define DIM     64
#define N_EDGES 1250000
#define TOTAL   (N_NODES * DIM)      // 16,000,000 elements
#define SLOTS   40                   // max active degree (Poisson(4) tail ~1e-18)

#define NT 256
#define SCAT_THREADS (N_EDGES / 4)                         // 312,500 (4 edges/thread)
#define SCAT_BLOCKS  ((SCAT_THREADS + NT - 1) / NT)        // 1221
#define COPY_THREADS (TOTAL / 8)                           // 2,000,000 (8 elems/thread)
#define COPY_BLOCKS  ((COPY_THREADS + NT - 1) / NT)        // 7813

// Device globals (no allocations allowed). Zero-initialized at module load.
// All gather sources stored fp16 (32 MB each).
__device__ __half   g_Eh[TOTAL];                            // fp16 embeds (layer-1 src)
__device__ __half   g_Bh[TOTAL];                            // layer-1 output
__device__ __half   g_Ah[TOTAL];                            // layer-2 output
__device__ int4     g_edge2[(size_t)N_NODES * (SLOTS / 2)]; // 2 edges per int4
__device__ unsigned g_fill[N_NODES];                        // cursor == count

// ---------------- helpers ----------------
struct f8 { float4 lo, hi; };

__device__ __forceinline__ f8 h8_to_f8(uint4 u) {
    f8 r;
    float2 a = __half22float2(*reinterpret_cast<__half2*>(&u.x));
    float2 b = __half22float2(*reinterpret_cast<__half2*>(&u.y));
    float2 c = __half22float2(*reinterpret_cast<__half2*>(&u.z));
    float2 d = __half22float2(*reinterpret_cast<__half2*>(&u.w));
    r.lo = make_float4(a.x, a.y, b.x, b.y);
    r.hi = make_float4(c.x, c.y, d.x, d.y);
    return r;
}
__device__ __forceinline__ uint4 f8_to_h8(float4 lo, float4 hi) {
    __half2 a = __floats2half2_rn(lo.x, lo.y);
    __half2 b = __floats2half2_rn(lo.z, lo.w);
    __half2 c = __floats2half2_rn(hi.x, hi.y);
    __half2 d = __floats2half2_rn(hi.z, hi.w);
    uint4 u;
    u.x = *reinterpret_cast<unsigned*>(&a);
    u.y = *reinterpret_cast<unsigned*>(&b);
    u.z = *reinterpret_cast<unsigned*>(&c);
    u.w = *reinterpret_cast<unsigned*>(&d);
    return u;
}

#define ACC8(acc_lo, acc_hi, v, u)  do {                       \
    f8 _x = h8_to_f8(u);                                       \
    acc_lo.x += (v) * _x.lo.x; acc_lo.y += (v) * _x.lo.y;      \
    acc_lo.z += (v) * _x.lo.z; acc_lo.w += (v) * _x.lo.w;      \
    acc_hi.x += (v) * _x.hi.x; acc_hi.y += (v) * _x.hi.y;      \
    acc_hi.z += (v) * _x.hi.z; acc_hi.w += (v) * _x.hi.w;      \
} while (0)

// ---------------- prep: scatter (4 edges/thread) + fp16 embed copy ----------------
// g_fill zero on entry: zero-init at load, re-zeroed by spmm<2> each replay.
// Meta stores col*8 (pre-scaled uint4-row offset) to shorten the spmm address chain.
__device__ __forceinline__ void put_edge(int r, int c, float v) {
    if (v != 0.f) {
        unsigned p = atomicAdd(&g_fill[r], 1u);
        if (p < SLOTS)
            reinterpret_cast<int2*>(g_edge2)[(size_t)r * SLOTS + p] =
                make_int2(c * 8, __float_as_int(v));
    }
}

__global__ void prep_kernel(const int*   __restrict__ row,
                            const int*   __restrict__ col,
                            const float* __restrict__ adj,
                            const float* __restrict__ msk,
                            const float* __restrict__ ue,
                            const float* __restrict__ ie) {
    if (blockIdx.x < SCAT_BLOCKS) {
        int i = blockIdx.x * NT + threadIdx.x;      // quad index
        if (i >= SCAT_THREADS) return;
        int4   r4 = __ldcs(reinterpret_cast<const int4*>(row) + i);
        int4   c4 = __ldcs(reinterpret_cast<const int4*>(col) + i);
        float4 a4 = __ldcs(reinterpret_cast<const float4*>(adj) + i);
        float4 m4 = __ldcs(reinterpret_cast<const float4*>(msk) + i);
        put_edge(r4.x, c4.x, a4.x * m4.x);
        put_edge(r4.y, c4.y, a4.y * m4.y);
        put_edge(r4.z, c4.z, a4.z * m4.z);
        put_edge(r4.w, c4.w, a4.w * m4.w);
    } else {
        // fp16 embed table: thread handles 8 consecutive elements.
        unsigned i = (blockIdx.x - SCAT_BLOCKS) * NT + threadIdx.x;
        if (i >= COPY_THREADS) return;
        unsigned e8 = i * 8;
        const unsigned UELEMS = U_NODES * DIM;      // 6.4M, divisible by 8
        const float4* src = (e8 < UELEMS)
            ? reinterpret_cast<const float4*>(ue) + (e8 >> 2)
            : reinterpret_cast<const float4*>(ie) + ((e8 - UELEMS) >> 2);
        float4 a = __ldcs(src);
        float4 b = __ldcs(src + 1);
        reinterpret_cast<uint4*>(g_Eh)[i] = f8_to_h8(a, b);
    }
}

// ---------------- fused SpMM layers (round-12 proven body) ----------------
// 8 threads per row (four rows per warp); thread t owns 8 halves = one uint4.
// MODE 0: gather g_Eh -> write g_Bh                                 (layer 1)
// MODE 1: gather g_Bh -> write g_Ah                                 (layer 2)
// MODE 2: gather g_Ah -> out = (Eh + B + A + acc)/4 (fp32), 0 fill  (layer 3)
// Meta .x fields are pre-scaled (col*8): gather address = curh + m.x + t.
template <int MODE>
__global__ void __launch_bounds__(256, 6)
spmm_kernel(float* __restrict__ out) {
    int gid = blockIdx.x * blockDim.x + threadIdx.x;
    int r   = gid >> 3;
    int t   = gid & 7;
    if (r >= N_NODES) return;

    const int4* ep2 = g_edge2 + (size_t)r * (SLOTS / 2);
    const uint4* curh = reinterpret_cast<const uint4*>(
        MODE == 0 ? g_Eh : (MODE == 1 ? g_Bh : g_Ah));

    // Independent front-batched loads: cnt + head metas, no mutual dependence.
    unsigned cnt = g_fill[r];
    int4 m01 = __ldg(ep2);        // edges 0,1
    int4 m23 = __ldg(ep2 + 1);    // edges 2,3
    if (cnt > SLOTS) cnt = SLOTS;

    float4 accLo = make_float4(0.f, 0.f, 0.f, 0.f);
    float4 accHi = accLo;

    // Head: 4 predicated 16B gathers fire as soon as metas arrive.
    {
        bool p0 = cnt > 0, p1 = cnt > 1, p2 = cnt > 2, p3 = cnt > 3;
        uint4 x0, x1, x2, x3;
        if (p0) x0 = __ldg(curh + (unsigned)m01.x + t);
        if (p1) x1 = __ldg(curh + (unsigned)m01.z + t);
        if (p2) x2 = __ldg(curh + (unsigned)m23.x + t);
        if (p3) x3 = __ldg(curh + (unsigned)m23.z + t);
        if (p0) ACC8(accLo, accHi, __int_as_float(m01.y), x0);
        if (p1) ACC8(accLo, accHi, __int_as_float(m01.w), x1);
        if (p2) ACC8(accLo, accHi, __int_as_float(m23.y), x2);
        if (p3) ACC8(accLo, accHi, __int_as_float(m23.w), x3);
    }

    // Tail: batch-4 predicated per iteration (deg 5-8 in one pass).
    for (unsigned e = 4; e < cnt; e += 4) {
        int4 mA = __ldg(ep2 + (e >> 1));
        int4 mB = __ldg(ep2 + (e >> 1) + 1);
        bool p1 = (e + 1) < cnt, p2 = (e + 2) < cnt, p3 = (e + 3) < cnt;
        uint4 x0, x1, x2, x3;
        x0 = __ldg(curh + (unsigned)mA.x + t);         // e < cnt guaranteed
        if (p1) x1 = __ldg(curh + (unsigned)mA.z + t);
        if (p2) x2 = __ldg(curh + (unsigned)mB.x + t);
        if (p3) x3 = __ldg(curh + (unsigned)mB.z + t);
        ACC8(accLo, accHi, __int_as_float(mA.y), x0);
        if (p1) ACC8(accLo, accHi, __int_as_float(mA.w), x1);
        if (p2) ACC8(accLo, accHi, __int_as_float(mB.y), x2);
        if (p3) ACC8(accLo, accHi, __int_as_float(mB.w), x3);
    }

    unsigned idx = (unsigned)(r * 8 + t);               // uint4 index
    if (MODE == 0) {
        reinterpret_cast<uint4*>(g_Bh)[idx] = f8_to_h8(accLo, accHi);
    } else if (MODE == 1) {
        reinterpret_cast<uint4*>(g_Ah)[idx] = f8_to_h8(accLo, accHi);
    } else {
        f8 em = h8_to_f8(__ldcs(reinterpret_cast<const uint4*>(g_Eh) + idx));
        f8 bb = h8_to_f8(__ldcs(reinterpret_cast<const uint4*>(g_Bh) + idx));
        f8 aa = h8_to_f8(__ldcs(reinterpret_cast<const uint4*>(g_Ah) + idx));
        float4 oLo, oHi;
        oLo.x = (em.lo.x + bb.lo.x + aa.lo.x + accLo.x) * 0.25f;
        oLo.y = (em.lo.y + bb.lo.y + aa.lo.y + accLo.y) * 0.25f;
        oLo.z = (em.lo.z + bb.lo.z + aa.lo.z + accLo.z) * 0.25f;
        oLo.w = (em.lo.w + bb.lo.w + aa.lo.w + accLo.w) * 0.25f;
        oHi.x = (em.hi.x + bb.hi.x + aa.hi.x + accHi.x) * 0.25f;
        oHi.y = (em.hi.y + bb.hi.y + aa.hi.y + accHi.y) * 0.25f;
        oHi.z = (em.hi.z + bb.hi.z + aa.hi.z + accHi.z) * 0.25f;
        oHi.w = (em.hi.w + bb.hi.w + aa.hi.w + accHi.w) * 0.25f;
        float4* o4 = reinterpret_cast<float4*>(out) + idx * 2;
        __stcs(o4,     oLo);
        __stcs(o4 + 1, oHi);
        if (t == 0) g_fill[r] = 0;                   // reset cursor for next replay
    }
}

extern "C" void kernel_launch(void* const* d_in, const int* in_sizes, int n_in,
                              void* d_out, int out_size) {
    const int*   row = (const int*)  d_in[0];
    const int*   col = (const int*)  d_in[1];
    const float* adj = (const float*)d_in[2];
    const float* msk = (const float*)d_in[3];
    const float* ue  = (const float*)d_in[4];
    const float* ie  = (const float*)d_in[5];
    float* out = (float*)d_out;

    const int gridRow = (N_NODES * 8 + NT - 1) / NT;   // 7813

    prep_kernel<<<SCAT_BLOCKS + COPY_BLOCKS, NT>>>(row, col, adj, msk, ue, ie);
    spmm_kernel<0><<<gridRow, NT>>>(out);
    spmm_kernel<1><<<gridRow, NT>>>(out);
    spmm_kernel<2><<<gridRow, NT>>>(out);
}

// round 17
// speedup vs baseline: 1.0446x; 1.0446x over previous
#include <cuda_runtime.h>
#include <cuda_fp16.h>
#include <cstdint>

#define U_NODES 100000
#define I_NODES 150000
#define N_NODES (U_NODES + I_NODES)
#define DIM     64
#define N_EDGES 1250000
#define TOTAL   (N_NODES * DIM)      // 16,000,000 elements
#define SLOTS   40                   // max active degree (Poisson(4) tail ~1e-18)

#define NT 256
#define SCAT_THREADS (N_EDGES / 2)                         // 625,000 (2 edges/thread)
#define SCAT_BLOCKS  ((SCAT_THREADS + NT - 1) / NT)        // 2442
#define COPY_THREADS (TOTAL / 8)                           // 2,000,000 (8 elems/thread)
#define COPY_BLOCKS  ((COPY_THREADS + NT - 1) / NT)        // 7813

// Device globals (no allocations allowed). Zero-initialized at module load.
// All gather sources stored fp16 (32 MB each).
__device__ __half   g_Eh[TOTAL];                            // fp16 embeds (layer-1 src)
__device__ __half   g_Bh[TOTAL];                            // layer-1 output
__device__ __half   g_Ah[TOTAL];                            // layer-2 output
__device__ int4     g_edge2[(size_t)N_NODES * (SLOTS / 2)]; // 2 edges per int4
__device__ unsigned g_fill[N_NODES];                        // cursor == count

// ---------------- helpers ----------------
struct f8 { float4 lo, hi; };

__device__ __forceinline__ f8 h8_to_f8(uint4 u) {
    f8 r;
    float2 a = __half22float2(*reinterpret_cast<__half2*>(&u.x));
    float2 b = __half22float2(*reinterpret_cast<__half2*>(&u.y));
    float2 c = __half22float2(*reinterpret_cast<__half2*>(&u.z));
    float2 d = __half22float2(*reinterpret_cast<__half2*>(&u.w));
    r.lo = make_float4(a.x, a.y, b.x, b.y);
    r.hi = make_float4(c.x, c.y, d.x, d.y);
    return r;
}
__device__ __forceinline__ uint4 f8_to_h8(float4 lo, float4 hi) {
    __half2 a = __floats2half2_rn(lo.x, lo.y);
    __half2 b = __floats2half2_rn(lo.z, lo.w);
    __half2 c = __floats2half2_rn(hi.x, hi.y);
    __half2 d = __floats2half2_rn(hi.z, hi.w);
    uint4 u;
    u.x = *reinterpret_cast<unsigned*>(&a);
    u.y = *reinterpret_cast<unsigned*>(&b);
    u.z = *reinterpret_cast<unsigned*>(&c);
    u.w = *reinterpret_cast<unsigned*>(&d);
    return u;
}

// ---------------- prep: scatter (2 edges/thread) + fp16 embed copy ----------------
// g_fill zero on entry: zero-init at load, re-zeroed by spmm<2> each replay.
__global__ void prep_kernel(const int*   __restrict__ row,
                            const int*   __restrict__ col,
                            const float* __restrict__ adj,
                            const float* __restrict__ msk,
                            const float* __restrict__ ue,
                            const float* __restrict__ ie) {
    if (blockIdx.x < SCAT_BLOCKS) {
        int i = blockIdx.x * NT + threadIdx.x;      // pair index
        if (i >= SCAT_THREADS) return;
        int2   r2 = __ldcs(reinterpret_cast<const int2*>(row) + i);
        int2   c2 = __ldcs(reinterpret_cast<const int2*>(col) + i);
        float2 a2 = __ldcs(reinterpret_cast<const float2*>(adj) + i);
        float2 m2 = __ldcs(reinterpret_cast<const float2*>(msk) + i);
        float v0 = a2.x * m2.x;
        float v1 = a2.y * m2.y;
        if (v0 != 0.f) {
            unsigned p = atomicAdd(&g_fill[r2.x], 1u);
            if (p < SLOTS)
                reinterpret_cast<int2*>(g_edge2)[(size_t)r2.x * SLOTS + p] =
                    make_int2(c2.x, __float_as_int(v0));
        }
        if (v1 != 0.f) {
            unsigned p = atomicAdd(&g_fill[r2.y], 1u);
            if (p < SLOTS)
                reinterpret_cast<int2*>(g_edge2)[(size_t)r2.y * SLOTS + p] =
                    make_int2(c2.y, __float_as_int(v1));
        }
    } else {
        // fp16 embed table: thread handles 8 consecutive elements.
        unsigned i = (blockIdx.x - SCAT_BLOCKS) * NT + threadIdx.x;
        if (i >= COPY_THREADS) return;
        unsigned e8 = i * 8;
        const unsigned UELEMS = U_NODES * DIM;      // 6.4M, divisible by 8
        const float4* src = (e8 < UELEMS)
            ? reinterpret_cast<const float4*>(ue) + (e8 >> 2)
            : reinterpret_cast<const float4*>(ie) + ((e8 - UELEMS) >> 2);
        float4 a = __ldcs(src);
        float4 b = __ldcs(src + 1);
        reinterpret_cast<uint4*>(g_Eh)[i] = f8_to_h8(a, b);
    }
}

// ---------------- fused SpMM layers (round-12 proven body) ----------------
// 8 threads per row (four rows per warp); thread t owns 8 halves = one uint4.
// MODE 0: gather g_Eh -> write g_Bh                                 (layer 1)
// MODE 1: gather g_Bh -> write g_Ah                                 (layer 2)
// MODE 2: gather g_Ah -> out = (Eh + B + A + acc)/4 (fp32), 0 fill  (layer 3)
#define ACC8(acc_lo, acc_hi, v, u)  do {                       \
    f8 _x = h8_to_f8(u);                                       \
    acc_lo.x += (v) * _x.lo.x; acc_lo.y += (v) * _x.lo.y;      \
    acc_lo.z += (v) * _x.lo.z; acc_lo.w += (v) * _x.lo.w;      \
    acc_hi.x += (v) * _x.hi.x; acc_hi.y += (v) * _x.hi.y;      \
    acc_hi.z += (v) * _x.hi.z; acc_hi.w += (v) * _x.hi.w;      \
} while (0)

template <int MODE>
__global__ void __launch_bounds__(256, 6)
spmm_kernel(float* __restrict__ out) {
    int gid = blockIdx.x * blockDim.x + threadIdx.x;
    int r   = gid >> 3;
    int t   = gid & 7;
    if (r >= N_NODES) return;

    const int4* ep2 = g_edge2 + (size_t)r * (SLOTS / 2);
    const uint4* curh = reinterpret_cast<const uint4*>(
        MODE == 0 ? g_Eh : (MODE == 1 ? g_Bh : g_Ah));

    // Independent front-batched loads: cnt + head metas, no mutual dependence.
    unsigned cnt = g_fill[r];
    int4 m01 = __ldg(ep2);        // edges 0,1
    int4 m23 = __ldg(ep2 + 1);    // edges 2,3
    if (cnt > SLOTS) cnt = SLOTS;

    float4 accLo = make_float4(0.f, 0.f, 0.f, 0.f);
    float4 accHi = accLo;

    // Head: 4 predicated 16B gathers fire as soon as metas arrive.
    {
        bool p0 = cnt > 0, p1 = cnt > 1, p2 = cnt > 2, p3 = cnt > 3;
        uint4 x0, x1, x2, x3;
        if (p0) x0 = __ldg(curh + (unsigned)(m01.x * 8) + t);
        if (p1) x1 = __ldg(curh + (unsigned)(m01.z * 8) + t);
        if (p2) x2 = __ldg(curh + (unsigned)(m23.x * 8) + t);
        if (p3) x3 = __ldg(curh + (unsigned)(m23.z * 8) + t);
        if (p0) ACC8(accLo, accHi, __int_as_float(m01.y), x0);
        if (p1) ACC8(accLo, accHi, __int_as_float(m01.w), x1);
        if (p2) ACC8(accLo, accHi, __int_as_float(m23.y), x2);
        if (p3) ACC8(accLo, accHi, __int_as_float(m23.w), x3);
    }

    // Tail: batch-4 predicated per iteration (deg 5-8 in one pass).
    for (unsigned e = 4; e < cnt; e += 4) {
        int4 mA = __ldg(ep2 + (e >> 1));
        int4 mB = __ldg(ep2 + (e >> 1) + 1);
        bool p1 = (e + 1) < cnt, p2 = (e + 2) < cnt, p3 = (e + 3) < cnt;
        uint4 x0, x1, x2, x3;
        x0 = __ldg(curh + (unsigned)(mA.x * 8) + t);   // e < cnt guaranteed
        if (p1) x1 = __ldg(curh + (unsigned)(mA.z * 8) + t);
        if (p2) x2 = __ldg(curh + (unsigned)(mB.x * 8) + t);
        if (p3) x3 = __ldg(curh + (unsigned)(mB.z * 8) + t);
        ACC8(accLo, accHi, __int_as_float(mA.y), x0);
        if (p1) ACC8(accLo, accHi, __int_as_float(mA.w), x1);
        if (p2) ACC8(accLo, accHi, __int_as_float(mB.y), x2);
        if (p3) ACC8(accLo, accHi, __int_as_float(mB.w), x3);
    }

    unsigned idx = (unsigned)(r * 8 + t);               // uint4 index
    if (MODE == 0) {
        reinterpret_cast<uint4*>(g_Bh)[idx] = f8_to_h8(accLo, accHi);
    } else if (MODE == 1) {
        reinterpret_cast<uint4*>(g_Ah)[idx] = f8_to_h8(accLo, accHi);
    } else {
        if (t == 0) g_fill[r] = 0;   // cursor reset: independent store, issue early
        f8 em = h8_to_f8(__ldcs(reinterpret_cast<const uint4*>(g_Eh) + idx));
        f8 bb = h8_to_f8(__ldcs(reinterpret_cast<const uint4*>(g_Bh) + idx));
        f8 aa = h8_to_f8(__ldcs(reinterpret_cast<const uint4*>(g_Ah) + idx));
        float4 oLo, oHi;
        oLo.x = (em.lo.x + bb.lo.x + aa.lo.x + accLo.x) * 0.25f;
        oLo.y = (em.lo.y + bb.lo.y + aa.lo.y + accLo.y) * 0.25f;
        oLo.z = (em.lo.z + bb.lo.z + aa.lo.z + accLo.z) * 0.25f;
        oLo.w = (em.lo.w + bb.lo.w + aa.lo.w + accLo.w) * 0.25f;
        oHi.x = (em.hi.x + bb.hi.x + aa.hi.x + accHi.x) * 0.25f;
        oHi.y = (em.hi.y + bb.hi.y + aa.hi.y + accHi.y) * 0.25f;
        oHi.z = (em.hi.z + bb.hi.z + aa.hi.z + accHi.z) * 0.25f;
        oHi.w = (em.hi.w + bb.hi.w + aa.hi.w + accHi.w) * 0.25f;
        float4* o4 = reinterpret_cast<float4*>(out) + idx * 2;
        __stcs(o4,     oLo);
        __stcs(o4 + 1, oHi);
    }
}

extern "C" void kernel_launch(void* const* d_in, const int* in_sizes, int n_in,
                              void* d_out, int out_size) {
    const int*   row = (const int*)  d_in[0];
    const int*   col = (const int*)  d_in[1];
    const float* adj = (const float*)d_in[2];
    const float* msk = (const float*)d_in[3];
    const float* ue  = (const float*)d_in[4];
    const float* ie  = (const float*)d_in[5];
    float* out = (float*)d_out;

    const int gridRow = (N_NODES * 8 + NT - 1) / NT;   // 7813

    prep_kernel<<<SCAT_BLOCKS + COPY_BLOCKS, NT>>>(row, col, adj, msk, ue, ie);
    spmm_kernel<0><<<gridRow, NT>>>(out);
    spmm_kernel<1><<<gridRow, NT>>>(out);
    spmm_kernel<2><<<gridRow, NT>>>(out);
}